// round 15
// baseline (speedup 1.0000x reference)
#include <cuda_runtime.h>
#include <cstdint>
#include <cfloat>

// Problem constants
#define B_    16
#define C_    512
#define HW_   784          // 28*28
#define P_    4
#define K_    2048
#define D_    128
#define N_    12544        // B_*HW_
#define NP_   50176        // N_*P_
#define MT    64           // m-rows per CTA in k_mma (halved: packing + occ)
#define MTILE 196          // 12544 / 64
#define TKC   32           // codes per chunk (double-buffered)
#define NCHUNK 64          // 2048/32
#define TN    64           // k_zq tile
#define NTILE 196

// d_out layout: [zq_out (6422528 f32)] [q_loss (1 f32)] [distance_prob (N_*P_*K_ f32)]
#define LOSS_OFF 6422528
#define PROB_OFF 6422529   // NOTE: odd -> prob base is only 4-byte aligned.
                           // All prob accesses MUST be scalar float.

#define EPS_RESCUE 2e-4f

// smem float offsets for k_mma (total 17472 floats = 69888 B; 3 CTAs/SM)
#define OFF_A    0                      // [64][132] tf32 bits (rna)
#define OFF_B0   (64 * 132)             // buffer 0: [32][132] raw fp32
#define OFF_B1   (OFF_B0 + 32 * 132)    // buffer 1
#define OFF_SSZ  (OFF_B1 + 32 * 132)    // [64]
#define OFF_SM1  (OFF_SSZ + 64)         // [128]
#define OFF_SK1  (OFF_SM1 + 128)
#define OFF_SM2  (OFF_SK1 + 128)
#define OFF_SK2  (OFF_SM2 + 128)
#define SMEM_FLOATS (OFF_SK2 + 128)

// Scratch (no allocations allowed)
__device__ float g_sc[P_ * K_];        // ||codebook row||^2 (exact fp32, ref order)
__device__ float g_minD[NP_];          // per (n*4+p) min dist (tf32-based)
__device__ int   g_idx[NP_];           // per (n*4+p) argmin k
__device__ float g_m2[NP_];            // runner-up dist
__device__ int   g_k2[NP_];            // runner-up index
__device__ float g_szv[NP_];           // exact sz per (n,p), ref order
__device__ float g_losspart[NTILE * P_];

__device__ __forceinline__ uint32_t f2tf32(float f) {
    uint32_t r;
    asm("cvt.rna.tf32.f32 %0, %1;" : "=r"(r) : "f"(f));
    return r;
}

__device__ __forceinline__ void mma_tf32(float acc[4], const uint32_t a[4],
                                         uint32_t b0, uint32_t b1) {
    asm volatile(
        "mma.sync.aligned.m16n8k8.row.col.f32.tf32.tf32.f32 "
        "{%0,%1,%2,%3},{%4,%5,%6,%7},{%8,%9},{%0,%1,%2,%3};"
        : "+f"(acc[0]), "+f"(acc[1]), "+f"(acc[2]), "+f"(acc[3])
        : "r"(a[0]), "r"(a[1]), "r"(a[2]), "r"(a[3]), "r"(b0), "r"(b1));
}

// ldmatrix x4 on 32-bit data: four 8-row x 16-byte windows.
__device__ __forceinline__ void ldsm4(uint32_t r[4], uint32_t addr) {
    asm volatile(
        "ldmatrix.sync.aligned.m8n8.x4.shared.b16 {%0,%1,%2,%3}, [%4];"
        : "=r"(r[0]), "=r"(r[1]), "=r"(r[2]), "=r"(r[3]) : "r"(addr));
}

__device__ __forceinline__ void cp16(uint32_t dst, const void* src) {
    asm volatile("cp.async.ca.shared.global [%0], [%1], 16;"
                 :: "r"(dst), "l"(src));
}
#define CP_COMMIT() asm volatile("cp.async.commit_group;" ::: "memory")
#define CP_WAIT1()  asm volatile("cp.async.wait_group 1;" ::: "memory")
#define CP_WAIT0()  asm volatile("cp.async.wait_group 0;" ::: "memory")

__device__ __forceinline__ bool better(float v, int k, float m, int km) {
    return v < m || (v == m && k < km);
}
// merge top-2 (b1,b2 sorted) into (a1,a2 sorted)
__device__ __forceinline__ void merge2(float& a1, int& ka1, float& a2, int& ka2,
                                       float b1, int kb1, float b2, int kb2) {
    if (better(b1, kb1, a1, ka1)) {
        float t1 = a1; int tk1 = ka1;
        a1 = b1; ka1 = kb1;
        if (better(t1, tk1, b2, kb2)) { a2 = t1; ka2 = tk1; }
        else                          { a2 = b2; ka2 = kb2; }
    } else if (better(b1, kb1, a2, ka2)) {
        a2 = b1; ka2 = kb1;
    }
}

// ---------------------------------------------------------------------------
// K0: per-codeword squared norm (exact fp32, sequential ref order)
__global__ void k_sc(const float* __restrict__ cb) {
    int t = blockIdx.x * 256 + threadIdx.x;
    const float* row = cb + (size_t)t * D_;
    float s = 0.f;
    for (int j = 0; j < D_; j++) {
        float q = __fmul_rn(row[j], row[j]);
        s = __fadd_rn(s, q);
    }
    g_sc[t] = s;
}

// no-op shim: keeps k_mma at profiled launch index 3
__global__ void k_nop() {}

// ---------------------------------------------------------------------------
// K1: tf32 mma.sync GEMM, MT=64 tiles. 8 warps = 4 m-warps(16 rows) x
// 2 k-warps(16 k). cp.async double-buffered B, ldmatrix feeding, RNA-fix
// (+0x1000) on raw fp32 B. 3 CTAs/SM -> 24 warps, and 784 tiles pack into
// 456 slots in 2 sub-waves (vs 392 tiles / 304 slots = 2 full waves before).
__global__ void __launch_bounds__(256, 3)
k_mma(const float* __restrict__ z, const float* __restrict__ cb,
      float* __restrict__ out) {
    extern __shared__ float sm[];
    uint32_t* sAu = (uint32_t*)(sm + OFF_A);
    float*    ssz = sm + OFF_SSZ;
    float*    sm1 = sm + OFF_SM1;
    int*      sk1 = (int*)(sm + OFF_SK1);
    float*    sm2 = sm + OFF_SM2;
    int*      sk2 = (int*)(sm + OFF_SK2);

    const int tid  = threadIdx.x;
    const int lane = tid & 31;
    const int wid  = tid >> 5;
    const int p    = blockIdx.y;
    const int n0   = blockIdx.x * MT;
    const int g    = lane >> 2;      // 0..7
    const int tig  = lane & 3;       // 0..3
    const int mw   = (wid & 3) * 16;        // warp m offset (4 m-warps)
    const int kw   = (wid >> 2) * 16;       // warp k offset (2 k-warps)

    const uint32_t bByte0 = (uint32_t)__cvta_generic_to_shared(sm + OFF_B0);
    const float* cbp = cb + (size_t)p * K_ * D_;

    // A tile load + tf32(rna) convert (each thread: one row, every 4th j)
    {
        int r = tid & 63, j0 = tid >> 6;
        int n = n0 + r, b = n / HW_, hw = n - b * HW_;
        const float* zr = z + (size_t)(b * C_ + p * D_) * HW_ + hw;
#pragma unroll 4
        for (int i = 0; i < 32; i++) {
            int j = j0 + 4 * i;
            sAu[r * 132 + j] = f2tf32(zr[(size_t)j * HW_]);
        }
    }

    // prefetch chunks 0 and 1 (16 KB each: 4 x 16B per thread)
#pragma unroll
    for (int c0 = 0; c0 < 2; c0++) {
        const float* src = cbp + (size_t)c0 * TKC * D_;
        uint32_t dstB = bByte0 + (uint32_t)(c0 * (32 * 132 * 4));
#pragma unroll
        for (int i = 0; i < 4; i++) {
            int e = tid + 256 * i;
            int kr = e >> 5, j4 = e & 31;
            cp16(dstB + (uint32_t)((kr * 132 + j4 * 4) * 4),
                 src + (size_t)kr * D_ + j4 * 4);
        }
        CP_COMMIT();
    }

    // exact sz, strict sequential order (matches reference reduction order)
    if (tid < 64) {
        int r = tid, n = n0 + r, b = n / HW_, hw = n - b * HW_;
        const float* zr = z + (size_t)(b * C_ + p * D_) * HW_ + hw;
        float s = 0.f;
        for (int j = 0; j < D_; j++) {
            float v = zr[(size_t)j * HW_];
            s = __fadd_rn(s, __fmul_rn(v, v));
        }
        ssz[r] = s;
        g_szv[(size_t)(n0 + r) * 4 + p] = s;
    }
    __syncthreads();

    // per-thread row sz cache (rows: mw + 8*rr + g, t = rr)
    float szr[2];
#pragma unroll
    for (int t = 0; t < 2; t++)
        szr[t] = ssz[mw + 8 * t + g];

    // ldmatrix lane-address setup (constant across chunks; +32B per k8-step)
    const int l7 = lane & 7;
    uint32_t aAddr;
    {
        // mats: {r0-7 d-lo, r8-15 d-lo, r0-7 d-hi, r8-15 d-hi} -> m16k8 frag
        int row = mw + 8 * ((lane >> 3) & 1) + l7;
        aAddr = (uint32_t)__cvta_generic_to_shared(sAu)
              + (uint32_t)((row * 132 + 4 * (lane >> 4)) * 4);
    }
    uint32_t bAddr[2];
    {
        // mats: {j0 d-lo, j0 d-hi, j1 d-lo, j1 d-hi}
        int row = kw + 8 * (lane >> 4) + l7;
        uint32_t o = (uint32_t)((row * 132 + 4 * ((lane >> 3) & 1)) * 4);
        bAddr[0] = bByte0 + o;
        bAddr[1] = bByte0 + (uint32_t)(32 * 132 * 4) + o;
    }

    float m1v[2], m2v[2];
    int   k1v[2], k2v[2];
#pragma unroll
    for (int t = 0; t < 2; t++) {
        m1v[t] = FLT_MAX; m2v[t] = FLT_MAX; k1v[t] = 0; k2v[t] = 0;
    }

    float* prob = out + PROB_OFF;
    const float* scg = g_sc + p * K_;

    for (int c = 0; c < NCHUNK; c++) {
        const int buf = c & 1;
        if (c < NCHUNK - 1) { CP_WAIT1(); } else { CP_WAIT0(); }
        __syncthreads();

        float acc[2][4];
#pragma unroll
        for (int j = 0; j < 2; j++)
#pragma unroll
            for (int q = 0; q < 4; q++) acc[j][q] = 0.f;

#pragma unroll
        for (int s = 0; s < 16; s++) {
            const uint32_t off = (uint32_t)(s * 32);   // 8 floats per k8-step
            uint32_t aa[4], bb[4];
            ldsm4(aa, aAddr + off);
            ldsm4(bb, bAddr[buf] + off);
            // RNA-equivalent rounding of raw fp32 B at the tf32 boundary
            bb[0] += 0x1000u; bb[1] += 0x1000u;
            bb[2] += 0x1000u; bb[3] += 0x1000u;
            mma_tf32(acc[0], aa, bb[0], bb[1]);
            mma_tf32(acc[1], aa, bb[2], bb[3]);
        }
        __syncthreads();   // all reads of buf done -> safe to overwrite

        // prefetch chunk c+2 into this buffer
        if (c + 2 < NCHUNK) {
            const float* src = cbp + (size_t)(c + 2) * TKC * D_;
            uint32_t dstB = bByte0 + (uint32_t)(buf * (32 * 132 * 4));
#pragma unroll
            for (int i = 0; i < 4; i++) {
                int e = tid + 256 * i;
                int kr = e >> 5, j4 = e & 31;
                cp16(dstB + (uint32_t)((kr * 132 + j4 * 4) * 4),
                     src + (size_t)kr * D_ + j4 * 4);
            }
        }
        CP_COMMIT();   // commit every chunk (possibly empty) to keep count

        // epilogue: dist, scalar streaming stores, top-2 update
        const int kc = c * TKC + kw;
#pragma unroll
        for (int rr = 0; rr < 2; rr++) {
            const float sz_ = szr[rr];
            const int rowg = n0 + mw + 8 * rr + g;
            float* prow = prob + (size_t)rowg * 8192 + p * 2048;
#pragma unroll
            for (int j = 0; j < 2; j++) {
                int k = kc + 8 * j + 2 * tig;
                float sc0 = __ldg(scg + k);
                float sc1 = __ldg(scg + k + 1);
                float d0v = __fmaf_rn(-2.f, acc[j][2 * rr],
                                      __fadd_rn(sz_, sc0));
                float d1v = __fmaf_rn(-2.f, acc[j][2 * rr + 1],
                                      __fadd_rn(sz_, sc1));
                __stcs(prow + k,     d0v);
                __stcs(prow + k + 1, d1v);
                if (better(d0v, k, m1v[rr], k1v[rr])) {
                    m2v[rr] = m1v[rr]; k2v[rr] = k1v[rr];
                    m1v[rr] = d0v;     k1v[rr] = k;
                } else if (better(d0v, k, m2v[rr], k2v[rr])) {
                    m2v[rr] = d0v; k2v[rr] = k;
                }
                if (better(d1v, k + 1, m1v[rr], k1v[rr])) {
                    m2v[rr] = m1v[rr]; k2v[rr] = k1v[rr];
                    m1v[rr] = d1v;     k1v[rr] = k + 1;
                } else if (better(d1v, k + 1, m2v[rr], k2v[rr])) {
                    m2v[rr] = d1v; k2v[rr] = k + 1;
                }
            }
        }
    }

    // quad merge (lanes sharing the same rows: same g, tig 0..3)
#pragma unroll
    for (int t = 0; t < 2; t++) {
#pragma unroll
        for (int off = 1; off <= 2; off <<= 1) {
            float o1 = __shfl_xor_sync(0xffffffffu, m1v[t], off);
            int  ok1 = __shfl_xor_sync(0xffffffffu, k1v[t], off);
            float o2 = __shfl_xor_sync(0xffffffffu, m2v[t], off);
            int  ok2 = __shfl_xor_sync(0xffffffffu, k2v[t], off);
            merge2(m1v[t], k1v[t], m2v[t], k2v[t], o1, ok1, o2, ok2);
        }
    }
    __syncthreads();
    if (tig == 0) {
        int kg = wid >> 2;   // 0..1
#pragma unroll
        for (int t = 0; t < 2; t++) {
            int row = mw + 8 * t + g;
            int idx = kg * 64 + row;
            sm1[idx] = m1v[t]; sk1[idx] = k1v[t];
            sm2[idx] = m2v[t]; sk2[idx] = k2v[t];
        }
    }
    __syncthreads();
    if (tid < 64) {
        float a1 = sm1[tid], a2 = sm2[tid];
        int  ka1 = sk1[tid], ka2 = sk2[tid];
        merge2(a1, ka1, a2, ka2, sm1[64 + tid], sk1[64 + tid],
               sm2[64 + tid], sk2[64 + tid]);
        size_t rho = (size_t)(n0 + tid) * 4 + p;
        g_minD[rho] = a1;
        g_idx[rho]  = ka1;
        g_m2[rho]   = a2;
        g_k2[rho]   = ka2;
    }
}

// ---------------------------------------------------------------------------
// K1b: exact-fp32 argmin rescue for near-tie rows. One warp per rho.
__global__ void __launch_bounds__(128)
k_rescue(const float* __restrict__ z, const float* __restrict__ cb) {
    int w    = threadIdx.x >> 5;
    int lane = threadIdx.x & 31;
    int rho  = blockIdx.x * 4 + w;
    float m1 = g_minD[rho];
    float m2 = g_m2[rho];
    if (!(m2 - m1 < EPS_RESCUE)) return;     // g_idx already correct

    int k1 = g_idx[rho], k2 = g_k2[rho];
    int n = rho >> 2, p = rho & 3;
    int b = n / HW_, hw = n - b * HW_;
    const float* zr  = z + (size_t)(b * C_ + p * D_) * HW_ + hw;
    const float* c1r = cb + (size_t)(p * K_ + k1) * D_;
    const float* c2r = cb + (size_t)(p * K_ + k2) * D_;

    float a1 = 0.f, a2 = 0.f;
#pragma unroll
    for (int t = 0; t < 4; t++) {
        int j = lane + 32 * t;
        float zv = zr[(size_t)j * HW_];
        a1 = __fmaf_rn(zv, c1r[j], a1);
        a2 = __fmaf_rn(zv, c2r[j], a2);
    }
    for (int o = 16; o; o >>= 1) {
        a1 += __shfl_xor_sync(0xffffffffu, a1, o);
        a2 += __shfl_xor_sync(0xffffffffu, a2, o);
    }
    if (lane == 0) {
        float sz = g_szv[rho];
        float d1 = __fmaf_rn(-2.f, a1, __fadd_rn(sz, g_sc[p * K_ + k1]));
        float d2 = __fmaf_rn(-2.f, a2, __fadd_rn(sz, g_sc[p * K_ + k2]));
        int pick = (d1 < d2 || (d1 == d2 && k1 < k2)) ? k1 : k2;
        g_idx[rho] = pick;
    }
}

// ---------------------------------------------------------------------------
// K2: in-place softmax normalize. One 64-thread group per row (4 rows/CTA).
__global__ void __launch_bounds__(256)
k_norm(float* __restrict__ out) {
    int g      = threadIdx.x >> 6;
    int lane64 = threadIdx.x & 63;
    int rho    = blockIdx.x * 4 + g;
    float* row = out + PROB_OFF + (size_t)rho * 2048;
    float m = g_minD[rho];

    float e[32];
    float s = 0.f;
#pragma unroll 4
    for (int ii = 0; ii < 32; ii++) {
        float dist = row[lane64 + 64 * ii];
        float ev = expf(2.f * (m - dist));
        e[ii] = ev;
        s += ev;
    }
    for (int o = 16; o; o >>= 1) s += __shfl_down_sync(0xffffffffu, s, o);
    __shared__ float wsum[8];
    if ((threadIdx.x & 31) == 0) wsum[threadIdx.x >> 5] = s;
    __syncthreads();
    float S = wsum[2 * g] + wsum[2 * g + 1];
    float inv = 1.0f / S;
#pragma unroll 4
    for (int ii = 0; ii < 32; ii++) row[lane64 + 64 * ii] = e[ii] * inv;
}

// ---------------------------------------------------------------------------
// K3: zq_out (straight-through, fl(zf + fl(zq - zf))) + per-CTA loss partials.
__global__ void __launch_bounds__(256)
k_zq(const float* __restrict__ z, const float* __restrict__ cb,
     float* __restrict__ out) {
    __shared__ float cz[TN][D_];
    __shared__ int   sidx[TN];
    __shared__ float lred[256];

    const int tile = blockIdx.x;
    const int p    = blockIdx.y;
    const int tid  = threadIdx.x;
    const int n0   = tile * TN;

    if (tid < TN) sidx[tid] = g_idx[(n0 + tid) * 4 + p];
    __syncthreads();

    for (int e = tid; e < TN * (D_ / 4); e += 256) {
        int r  = e >> 5;
        int j4 = e & 31;
        float4 v = *(const float4*)(cb + ((size_t)(p * K_ + sidx[r]) * D_) + j4 * 4);
        cz[r][j4 * 4 + 0] = v.x; cz[r][j4 * 4 + 1] = v.y;
        cz[r][j4 * 4 + 2] = v.z; cz[r][j4 * 4 + 3] = v.w;
    }
    __syncthreads();

    float ls = 0.f;
    for (int e = tid; e < TN * D_; e += 256) {
        int j = e >> 6;
        int r = e & 63;
        int n = n0 + r;
        int b = n / HW_;
        int hw = n - b * HW_;
        size_t ga = (size_t)(b * C_ + p * D_ + j) * HW_ + hw;
        float zf = z[ga];
        float d  = __fsub_rn(cz[r][j], zf);
        out[ga]  = __fadd_rn(zf, d);
        ls = __fadd_rn(ls, __fmul_rn(d, d));
    }
    lred[tid] = ls;
    __syncthreads();
    for (int o = 128; o; o >>= 1) {
        if (tid < o) lred[tid] += lred[tid + o];
        __syncthreads();
    }
    if (tid == 0) g_losspart[p * NTILE + tile] = lred[0];
}

// ---------------------------------------------------------------------------
// K4: final deterministic loss reduction. q = m + fl(0.25*m).
__global__ void k_loss(float* __restrict__ out) {
    __shared__ float s[256];
    int tid = threadIdx.x;
    float a = 0.f;
    for (int e = tid; e < NTILE * P_; e += 256) a += g_losspart[e];
    s[tid] = a;
    __syncthreads();
    for (int o = 128; o; o >>= 1) {
        if (tid < o) s[tid] += s[tid + o];
        __syncthreads();
    }
    if (tid == 0) {
        float m = s[0] / 6422528.0f;
        out[LOSS_OFF] = __fadd_rn(m, __fmul_rn(0.25f, m));
    }
}

// ---------------------------------------------------------------------------
extern "C" void kernel_launch(void* const* d_in, const int* in_sizes, int n_in,
                              void* d_out, int out_size) {
    const float* z  = (const float*)d_in[0];   // [16,512,28,28]
    const float* cb = (const float*)d_in[1];   // [4,2048,128]
    float* out = (float*)d_out;

    const int smem_mma = SMEM_FLOATS * (int)sizeof(float);
    cudaFuncSetAttribute(k_mma, cudaFuncAttributeMaxDynamicSharedMemorySize, smem_mma);

    k_sc<<<32, 256>>>(cb);
    k_nop<<<1, 32>>>();          // shims: keep k_mma at profiled launch idx 3
    k_nop<<<1, 32>>>();
    k_mma<<<dim3(MTILE, P_), 256, smem_mma>>>(z, cb, out);
    k_rescue<<<NP_ / 4, 128>>>(z, cb);
    k_norm<<<N_, 256>>>(out);
    k_zq<<<dim3(NTILE, P_), 256>>>(z, cb, out);
    k_loss<<<1, 256>>>(out);
}

// round 16
// speedup vs baseline: 1.0055x; 1.0055x over previous
#include <cuda_runtime.h>
#include <cstdint>
#include <cfloat>

// Problem constants
#define B_    16
#define C_    512
#define HW_   784          // 28*28
#define P_    4
#define K_    2048
#define D_    128
#define N_    12544        // B_*HW_
#define NP_   50176        // N_*P_
#define MT    64           // m-rows per CTA in k_mma
#define MTILE 196          // 12544 / 64
#define TKC   64           // codes per chunk (double-buffered)
#define NCHUNK 32          // 2048/64
#define TN    64           // k_zq tile
#define NTILE 196

// d_out layout: [zq_out (6422528 f32)] [q_loss (1 f32)] [distance_prob (N_*P_*K_ f32)]
#define LOSS_OFF 6422528
#define PROB_OFF 6422529   // NOTE: odd -> prob base is only 4-byte aligned.
                           // All prob accesses MUST be scalar float.

#define EPS_RESCUE 2e-4f

// smem float offsets for k_mma (total ~25984 fl = 103936 B; 2 CTAs/SM)
#define OFF_A    0                      // [64][132] tf32 bits (rna)
#define OFF_B0   (64 * 132)             // buffer 0: [64][132] raw fp32
#define OFF_B1   (OFF_B0 + 64 * 132)    // buffer 1
#define OFF_SSZ  (OFF_B1 + 64 * 132)    // [64]
#define OFF_SM1  (OFF_SSZ + 64)         // [128] (2 kg x 64 rows)
#define OFF_SK1  (OFF_SM1 + 128)
#define OFF_SM2  (OFF_SK1 + 128)
#define OFF_SK2  (OFF_SM2 + 128)
#define SMEM_FLOATS (OFF_SK2 + 128)

// Scratch (no allocations allowed)
__device__ float g_sc[P_ * K_];        // ||codebook row||^2 (exact fp32, ref order)
__device__ float g_minD[NP_];          // per (n*4+p) min dist (tf32-based)
__device__ int   g_idx[NP_];           // per (n*4+p) argmin k
__device__ float g_m2[NP_];            // runner-up dist
__device__ int   g_k2[NP_];            // runner-up index
__device__ float g_szv[NP_];           // exact sz per (n,p), ref order
__device__ float g_losspart[NTILE * P_];

__device__ __forceinline__ uint32_t f2tf32(float f) {
    uint32_t r;
    asm("cvt.rna.tf32.f32 %0, %1;" : "=r"(r) : "f"(f));
    return r;
}

__device__ __forceinline__ void mma_tf32(float acc[4], const uint32_t a[4],
                                         uint32_t b0, uint32_t b1) {
    asm volatile(
        "mma.sync.aligned.m16n8k8.row.col.f32.tf32.tf32.f32 "
        "{%0,%1,%2,%3},{%4,%5,%6,%7},{%8,%9},{%0,%1,%2,%3};"
        : "+f"(acc[0]), "+f"(acc[1]), "+f"(acc[2]), "+f"(acc[3])
        : "r"(a[0]), "r"(a[1]), "r"(a[2]), "r"(a[3]), "r"(b0), "r"(b1));
}

// ldmatrix x4 on 32-bit data: four 8-row x 16-byte windows.
__device__ __forceinline__ void ldsm4(uint32_t r[4], uint32_t addr) {
    asm volatile(
        "ldmatrix.sync.aligned.m8n8.x4.shared.b16 {%0,%1,%2,%3}, [%4];"
        : "=r"(r[0]), "=r"(r[1]), "=r"(r[2]), "=r"(r[3]) : "r"(addr));
}

__device__ __forceinline__ void cp16(uint32_t dst, const void* src) {
    asm volatile("cp.async.ca.shared.global [%0], [%1], 16;"
                 :: "r"(dst), "l"(src));
}
#define CP_COMMIT() asm volatile("cp.async.commit_group;" ::: "memory")
#define CP_WAIT1()  asm volatile("cp.async.wait_group 1;" ::: "memory")
#define CP_WAIT0()  asm volatile("cp.async.wait_group 0;" ::: "memory")

__device__ __forceinline__ bool better(float v, int k, float m, int km) {
    return v < m || (v == m && k < km);
}
// merge top-2 (b1,b2 sorted) into (a1,a2 sorted)
__device__ __forceinline__ void merge2(float& a1, int& ka1, float& a2, int& ka2,
                                       float b1, int kb1, float b2, int kb2) {
    if (better(b1, kb1, a1, ka1)) {
        float t1 = a1; int tk1 = ka1;
        a1 = b1; ka1 = kb1;
        if (better(t1, tk1, b2, kb2)) { a2 = t1; ka2 = tk1; }
        else                          { a2 = b2; ka2 = kb2; }
    } else if (better(b1, kb1, a2, ka2)) {
        a2 = b1; ka2 = kb1;
    }
}

// ---------------------------------------------------------------------------
// K0: per-codeword squared norm (exact fp32, sequential ref order)
__global__ void k_sc(const float* __restrict__ cb) {
    int t = blockIdx.x * 256 + threadIdx.x;
    const float* row = cb + (size_t)t * D_;
    float s = 0.f;
    for (int j = 0; j < D_; j++) {
        float q = __fmul_rn(row[j], row[j]);
        s = __fadd_rn(s, q);
    }
    g_sc[t] = s;
}

// no-op shim: keeps k_mma at profiled launch index 3
__global__ void k_nop() {}

// ---------------------------------------------------------------------------
// K1: tf32 mma.sync GEMM. 128 threads = 4 warps (2m x 2k), warp tile 32x32
// (0.25 B/MAC smem traffic vs 0.375/0.5 in R14/R15 -> L1-bound improvement).
// MT=64, TKC=64 double-buffered cp.async, ldmatrix feeding, RNA-fix (+0x1000)
// on raw fp32 B. 2 CTAs/SM; 784 CTAs / 304 slots = 2.58 -> 3 balanced waves.
__global__ void __launch_bounds__(128, 2)
k_mma(const float* __restrict__ z, const float* __restrict__ cb,
      float* __restrict__ out) {
    extern __shared__ float sm[];
    uint32_t* sAu = (uint32_t*)(sm + OFF_A);
    float*    ssz = sm + OFF_SSZ;
    float*    sm1 = sm + OFF_SM1;
    int*      sk1 = (int*)(sm + OFF_SK1);
    float*    sm2 = sm + OFF_SM2;
    int*      sk2 = (int*)(sm + OFF_SK2);

    const int tid  = threadIdx.x;
    const int lane = tid & 31;
    const int wid  = tid >> 5;       // 0..3
    const int p    = blockIdx.y;
    const int n0   = blockIdx.x * MT;
    const int g    = lane >> 2;      // 0..7
    const int tig  = lane & 3;       // 0..3
    const int mw   = (wid & 1) * 32;        // warp m offset (2 m-warps)
    const int kw   = ((wid >> 1) & 1) * 32; // warp k offset (2 k-warps)

    const uint32_t bByte0 = (uint32_t)__cvta_generic_to_shared(sm + OFF_B0);
    const float* cbp = cb + (size_t)p * K_ * D_;

    // A tile load + tf32(rna) convert (each thread: one row, every other j)
    {
        int r = tid & 63, j0 = tid >> 6;
        int n = n0 + r, b = n / HW_, hw = n - b * HW_;
        const float* zr = z + (size_t)(b * C_ + p * D_) * HW_ + hw;
#pragma unroll 4
        for (int i = 0; i < 64; i++) {
            int j = j0 + 2 * i;
            sAu[r * 132 + j] = f2tf32(zr[(size_t)j * HW_]);
        }
    }

    // prefetch chunks 0 and 1 (32 KB each: 16 x 16B per thread)
#pragma unroll
    for (int c0 = 0; c0 < 2; c0++) {
        const float* src = cbp + (size_t)c0 * TKC * D_;
        uint32_t dstB = bByte0 + (uint32_t)(c0 * (64 * 132 * 4));
#pragma unroll
        for (int i = 0; i < 16; i++) {
            int e = tid + 128 * i;
            int kr = e >> 5, j4 = e & 31;
            cp16(dstB + (uint32_t)((kr * 132 + j4 * 4) * 4),
                 src + (size_t)kr * D_ + j4 * 4);
        }
        CP_COMMIT();
    }

    // exact sz, strict sequential order (matches reference reduction order)
    if (tid < 64) {
        int r = tid, n = n0 + r, b = n / HW_, hw = n - b * HW_;
        const float* zr = z + (size_t)(b * C_ + p * D_) * HW_ + hw;
        float s = 0.f;
        for (int j = 0; j < D_; j++) {
            float v = zr[(size_t)j * HW_];
            s = __fadd_rn(s, __fmul_rn(v, v));
        }
        ssz[r] = s;
        g_szv[(size_t)(n0 + r) * 4 + p] = s;
    }
    __syncthreads();

    // per-thread row sz cache (t=2*mi+rr: row = mw + 16*mi + 8*rr + g)
    float szr[4];
#pragma unroll
    for (int t = 0; t < 4; t++)
        szr[t] = ssz[mw + 16 * (t >> 1) + 8 * (t & 1) + g];

    // ldmatrix lane-address setup (constant across chunks; +32B per k8-step)
    const int l7 = lane & 7;
    uint32_t aAddr[2];
    {
        int row = mw + 8 * ((lane >> 3) & 1) + l7;
        uint32_t base = (uint32_t)__cvta_generic_to_shared(sAu);
        uint32_t o = (uint32_t)((row * 132 + 4 * (lane >> 4)) * 4);
        aAddr[0] = base + o;                         // rows mw..mw+15
        aAddr[1] = base + o + 16u * 132u * 4u;       // rows mw+16..mw+31
    }
    uint32_t bAddr[2][2];   // [buf][bg]
    {
        int row = kw + 8 * (lane >> 4) + l7;
        uint32_t o = (uint32_t)((row * 132 + 4 * ((lane >> 3) & 1)) * 4);
#pragma unroll
        for (int buf = 0; buf < 2; buf++) {
            uint32_t b0 = bByte0 + (uint32_t)(buf * (64 * 132 * 4)) + o;
            bAddr[buf][0] = b0;                      // k kw..kw+15
            bAddr[buf][1] = b0 + 16u * 132u * 4u;    // k kw+16..kw+31
        }
    }

    float m1v[4], m2v[4];
    int   k1v[4], k2v[4];
#pragma unroll
    for (int t = 0; t < 4; t++) {
        m1v[t] = FLT_MAX; m2v[t] = FLT_MAX; k1v[t] = 0; k2v[t] = 0;
    }

    float* prob = out + PROB_OFF;
    const float* scg = g_sc + p * K_;

    for (int c = 0; c < NCHUNK; c++) {
        const int buf = c & 1;
        if (c < NCHUNK - 1) { CP_WAIT1(); } else { CP_WAIT0(); }
        __syncthreads();

        float acc[2][4][4];   // [mi][2*bg+jp][quad]
#pragma unroll
        for (int mi = 0; mi < 2; mi++)
#pragma unroll
            for (int j = 0; j < 4; j++)
#pragma unroll
                for (int q = 0; q < 4; q++) acc[mi][j][q] = 0.f;

#pragma unroll
        for (int s = 0; s < 16; s++) {
            const uint32_t off = (uint32_t)(s * 32);   // 8 floats per k8-step
            uint32_t aa0[4], aa1[4], bb0[4], bb1[4];
            ldsm4(aa0, aAddr[0] + off);
            ldsm4(aa1, aAddr[1] + off);
            ldsm4(bb0, bAddr[buf][0] + off);
            ldsm4(bb1, bAddr[buf][1] + off);
            // RNA-equivalent rounding of raw fp32 B at the tf32 boundary
            bb0[0] += 0x1000u; bb0[1] += 0x1000u;
            bb0[2] += 0x1000u; bb0[3] += 0x1000u;
            bb1[0] += 0x1000u; bb1[1] += 0x1000u;
            bb1[2] += 0x1000u; bb1[3] += 0x1000u;
            mma_tf32(acc[0][0], aa0, bb0[0], bb0[1]);
            mma_tf32(acc[1][0], aa1, bb0[0], bb0[1]);
            mma_tf32(acc[0][1], aa0, bb0[2], bb0[3]);
            mma_tf32(acc[1][1], aa1, bb0[2], bb0[3]);
            mma_tf32(acc[0][2], aa0, bb1[0], bb1[1]);
            mma_tf32(acc[1][2], aa1, bb1[0], bb1[1]);
            mma_tf32(acc[0][3], aa0, bb1[2], bb1[3]);
            mma_tf32(acc[1][3], aa1, bb1[2], bb1[3]);
        }
        __syncthreads();   // all reads of buf done -> safe to overwrite

        // prefetch chunk c+2 into this buffer (overlaps with epilogue below)
        if (c + 2 < NCHUNK) {
            const float* src = cbp + (size_t)(c + 2) * TKC * D_;
            uint32_t dstB = bByte0 + (uint32_t)(buf * (64 * 132 * 4));
#pragma unroll
            for (int i = 0; i < 16; i++) {
                int e = tid + 128 * i;
                int kr = e >> 5, j4 = e & 31;
                cp16(dstB + (uint32_t)((kr * 132 + j4 * 4) * 4),
                     src + (size_t)kr * D_ + j4 * 4);
            }
        }
        CP_COMMIT();   // commit every chunk (possibly empty) to keep count

        // epilogue: dist, scalar streaming stores, top-2 update
        const int kc = c * TKC + kw;
#pragma unroll
        for (int mi = 0; mi < 2; mi++) {
#pragma unroll
            for (int rr = 0; rr < 2; rr++) {
                const int t = 2 * mi + rr;
                const float sz_ = szr[t];
                const int rowg = n0 + mw + 16 * mi + 8 * rr + g;
                float* prow = prob + (size_t)rowg * 8192 + p * 2048;
#pragma unroll
                for (int j = 0; j < 4; j++) {   // j = 2*bg + jp
                    int k = kc + 16 * (j >> 1) + 8 * (j & 1) + 2 * tig;
                    float sc0 = __ldg(scg + k);
                    float sc1 = __ldg(scg + k + 1);
                    float d0v = __fmaf_rn(-2.f, acc[mi][j][2 * rr],
                                          __fadd_rn(sz_, sc0));
                    float d1v = __fmaf_rn(-2.f, acc[mi][j][2 * rr + 1],
                                          __fadd_rn(sz_, sc1));
                    __stcs(prow + k,     d0v);
                    __stcs(prow + k + 1, d1v);
                    if (better(d0v, k, m1v[t], k1v[t])) {
                        m2v[t] = m1v[t]; k2v[t] = k1v[t];
                        m1v[t] = d0v;    k1v[t] = k;
                    } else if (better(d0v, k, m2v[t], k2v[t])) {
                        m2v[t] = d0v; k2v[t] = k;
                    }
                    if (better(d1v, k + 1, m1v[t], k1v[t])) {
                        m2v[t] = m1v[t]; k2v[t] = k1v[t];
                        m1v[t] = d1v;    k1v[t] = k + 1;
                    } else if (better(d1v, k + 1, m2v[t], k2v[t])) {
                        m2v[t] = d1v; k2v[t] = k + 1;
                    }
                }
            }
        }
    }

    // quad merge (lanes sharing the same rows: same g, tig 0..3)
#pragma unroll
    for (int t = 0; t < 4; t++) {
#pragma unroll
        for (int off = 1; off <= 2; off <<= 1) {
            float o1 = __shfl_xor_sync(0xffffffffu, m1v[t], off);
            int  ok1 = __shfl_xor_sync(0xffffffffu, k1v[t], off);
            float o2 = __shfl_xor_sync(0xffffffffu, m2v[t], off);
            int  ok2 = __shfl_xor_sync(0xffffffffu, k2v[t], off);
            merge2(m1v[t], k1v[t], m2v[t], k2v[t], o1, ok1, o2, ok2);
        }
    }
    __syncthreads();
    if (tig == 0) {
        int kg = (wid >> 1) & 1;
#pragma unroll
        for (int t = 0; t < 4; t++) {
            int row = mw + 16 * (t >> 1) + 8 * (t & 1) + g;
            int idx = kg * 64 + row;
            sm1[idx] = m1v[t]; sk1[idx] = k1v[t];
            sm2[idx] = m2v[t]; sk2[idx] = k2v[t];
        }
    }
    __syncthreads();
    if (tid < 64) {
        float a1 = sm1[tid], a2 = sm2[tid];
        int  ka1 = sk1[tid], ka2 = sk2[tid];
        merge2(a1, ka1, a2, ka2, sm1[64 + tid], sk1[64 + tid],
               sm2[64 + tid], sk2[64 + tid]);
        size_t rho = (size_t)(n0 + tid) * 4 + p;
        g_minD[rho] = a1;
        g_idx[rho]  = ka1;
        g_m2[rho]   = a2;
        g_k2[rho]   = ka2;
    }
}

// ---------------------------------------------------------------------------
// K1b: exact-fp32 argmin rescue for near-tie rows. One warp per rho.
__global__ void __launch_bounds__(128)
k_rescue(const float* __restrict__ z, const float* __restrict__ cb) {
    int w    = threadIdx.x >> 5;
    int lane = threadIdx.x & 31;
    int rho  = blockIdx.x * 4 + w;
    float m1 = g_minD[rho];
    float m2 = g_m2[rho];
    if (!(m2 - m1 < EPS_RESCUE)) return;     // g_idx already correct

    int k1 = g_idx[rho], k2 = g_k2[rho];
    int n = rho >> 2, p = rho & 3;
    int b = n / HW_, hw = n - b * HW_;
    const float* zr  = z + (size_t)(b * C_ + p * D_) * HW_ + hw;
    const float* c1r = cb + (size_t)(p * K_ + k1) * D_;
    const float* c2r = cb + (size_t)(p * K_ + k2) * D_;

    float a1 = 0.f, a2 = 0.f;
#pragma unroll
    for (int t = 0; t < 4; t++) {
        int j = lane + 32 * t;
        float zv = zr[(size_t)j * HW_];
        a1 = __fmaf_rn(zv, c1r[j], a1);
        a2 = __fmaf_rn(zv, c2r[j], a2);
    }
    for (int o = 16; o; o >>= 1) {
        a1 += __shfl_xor_sync(0xffffffffu, a1, o);
        a2 += __shfl_xor_sync(0xffffffffu, a2, o);
    }
    if (lane == 0) {
        float sz = g_szv[rho];
        float d1 = __fmaf_rn(-2.f, a1, __fadd_rn(sz, g_sc[p * K_ + k1]));
        float d2 = __fmaf_rn(-2.f, a2, __fadd_rn(sz, g_sc[p * K_ + k2]));
        int pick = (d1 < d2 || (d1 == d2 && k1 < k2)) ? k1 : k2;
        g_idx[rho] = pick;
    }
}

// ---------------------------------------------------------------------------
// K2: in-place softmax normalize. One 64-thread group per row (4 rows/CTA).
__global__ void __launch_bounds__(256)
k_norm(float* __restrict__ out) {
    int g      = threadIdx.x >> 6;
    int lane64 = threadIdx.x & 63;
    int rho    = blockIdx.x * 4 + g;
    float* row = out + PROB_OFF + (size_t)rho * 2048;
    float m = g_minD[rho];

    float e[32];
    float s = 0.f;
#pragma unroll 4
    for (int ii = 0; ii < 32; ii++) {
        float dist = row[lane64 + 64 * ii];
        float ev = expf(2.f * (m - dist));
        e[ii] = ev;
        s += ev;
    }
    for (int o = 16; o; o >>= 1) s += __shfl_down_sync(0xffffffffu, s, o);
    __shared__ float wsum[8];
    if ((threadIdx.x & 31) == 0) wsum[threadIdx.x >> 5] = s;
    __syncthreads();
    float S = wsum[2 * g] + wsum[2 * g + 1];
    float inv = 1.0f / S;
#pragma unroll 4
    for (int ii = 0; ii < 32; ii++) row[lane64 + 64 * ii] = e[ii] * inv;
}

// ---------------------------------------------------------------------------
// K3: zq_out (straight-through, fl(zf + fl(zq - zf))) + per-CTA loss partials.
__global__ void __launch_bounds__(256)
k_zq(const float* __restrict__ z, const float* __restrict__ cb,
     float* __restrict__ out) {
    __shared__ float cz[TN][D_];
    __shared__ int   sidx[TN];
    __shared__ float lred[256];

    const int tile = blockIdx.x;
    const int p    = blockIdx.y;
    const int tid  = threadIdx.x;
    const int n0   = tile * TN;

    if (tid < TN) sidx[tid] = g_idx[(n0 + tid) * 4 + p];
    __syncthreads();

    for (int e = tid; e < TN * (D_ / 4); e += 256) {
        int r  = e >> 5;
        int j4 = e & 31;
        float4 v = *(const float4*)(cb + ((size_t)(p * K_ + sidx[r]) * D_) + j4 * 4);
        cz[r][j4 * 4 + 0] = v.x; cz[r][j4 * 4 + 1] = v.y;
        cz[r][j4 * 4 + 2] = v.z; cz[r][j4 * 4 + 3] = v.w;
    }
    __syncthreads();

    float ls = 0.f;
    for (int e = tid; e < TN * D_; e += 256) {
        int j = e >> 6;
        int r = e & 63;
        int n = n0 + r;
        int b = n / HW_;
        int hw = n - b * HW_;
        size_t ga = (size_t)(b * C_ + p * D_ + j) * HW_ + hw;
        float zf = z[ga];
        float d  = __fsub_rn(cz[r][j], zf);
        out[ga]  = __fadd_rn(zf, d);
        ls = __fadd_rn(ls, __fmul_rn(d, d));
    }
    lred[tid] = ls;
    __syncthreads();
    for (int o = 128; o; o >>= 1) {
        if (tid < o) lred[tid] += lred[tid + o];
        __syncthreads();
    }
    if (tid == 0) g_losspart[p * NTILE + tile] = lred[0];
}

// ---------------------------------------------------------------------------
// K4: final deterministic loss reduction. q = m + fl(0.25*m).
__global__ void k_loss(float* __restrict__ out) {
    __shared__ float s[256];
    int tid = threadIdx.x;
    float a = 0.f;
    for (int e = tid; e < NTILE * P_; e += 256) a += g_losspart[e];
    s[tid] = a;
    __syncthreads();
    for (int o = 128; o; o >>= 1) {
        if (tid < o) s[tid] += s[tid + o];
        __syncthreads();
    }
    if (tid == 0) {
        float m = s[0] / 6422528.0f;
        out[LOSS_OFF] = __fadd_rn(m, __fmul_rn(0.25f, m));
    }
}

// ---------------------------------------------------------------------------
extern "C" void kernel_launch(void* const* d_in, const int* in_sizes, int n_in,
                              void* d_out, int out_size) {
    const float* z  = (const float*)d_in[0];   // [16,512,28,28]
    const float* cb = (const float*)d_in[1];   // [4,2048,128]
    float* out = (float*)d_out;

    const int smem_mma = SMEM_FLOATS * (int)sizeof(float);
    cudaFuncSetAttribute(k_mma, cudaFuncAttributeMaxDynamicSharedMemorySize, smem_mma);

    k_sc<<<32, 256>>>(cb);
    k_nop<<<1, 32>>>();          // shims: keep k_mma at profiled launch idx 3
    k_nop<<<1, 32>>>();
    k_mma<<<dim3(MTILE, P_), 128, smem_mma>>>(z, cb, out);
    k_rescue<<<NP_ / 4, 128>>>(z, cb);
    k_norm<<<N_, 256>>>(out);
    k_zq<<<dim3(NTILE, P_), 256>>>(z, cb, out);
    k_loss<<<1, 256>>>(out);
}

// round 17
// speedup vs baseline: 1.1122x; 1.1060x over previous
#include <cuda_runtime.h>
#include <cstdint>
#include <cfloat>

// Problem constants
#define B_    16
#define C_    512
#define HW_   784          // 28*28
#define P_    4
#define K_    2048
#define D_    128
#define N_    12544        // B_*HW_
#define NP_   50176        // N_*P_
#define MT    128          // m-rows per CTA in k_mma
#define MTILE 98           // 12544 / 128
#define KH    1024         // k-range per CTA (K split in 2 halves)
#define TKC   32           // codes per chunk (double-buffered)
#define NCHUNK 32          // KH/TKC
#define TN    64           // k_zq tile
#define NTILE 196

// d_out layout: [zq_out (6422528 f32)] [q_loss (1 f32)] [distance_prob (N_*P_*K_ f32)]
#define LOSS_OFF 6422528
#define PROB_OFF 6422529   // NOTE: odd -> prob base is only 4-byte aligned.
                           // All prob accesses MUST be scalar float.

#define EPS_RESCUE 2e-4f

// smem float offsets for k_mma (R14 footprint: ~104 KB, 2 CTAs/SM)
#define OFF_A    0                      // [128][132] tf32 bits (rna)
#define OFF_B0   (128 * 132)            // buffer 0: [32][132] raw fp32
#define OFF_B1   (OFF_B0 + 32 * 132)    // buffer 1
#define OFF_SSZ  (OFF_B1 + 32 * 132)    // [128]
#define OFF_SM1  (OFF_SSZ + 128)        // [256]
#define OFF_SK1  (OFF_SM1 + 256)
#define OFF_SM2  (OFF_SK1 + 256)
#define OFF_SK2  (OFF_SM2 + 256)
#define SMEM_FLOATS (OFF_SK2 + 256)

// Scratch (no allocations allowed)
__device__ float g_sc[P_ * K_];        // ||codebook row||^2 (exact fp32, ref order)
__device__ float g_minD[NP_];          // merged min dist (written by k_rescue)
__device__ int   g_idx[NP_];           // merged+rescued argmin
__device__ float g_szv[NP_];           // exact sz per (n,p), ref order
__device__ float g_m1h[NP_ * 2];       // per-half top-1 dist
__device__ int   g_k1h[NP_ * 2];
__device__ float g_m2h[NP_ * 2];       // per-half top-2 dist
__device__ int   g_k2h[NP_ * 2];
__device__ float g_losspart[NTILE * P_];

__device__ __forceinline__ uint32_t f2tf32(float f) {
    uint32_t r;
    asm("cvt.rna.tf32.f32 %0, %1;" : "=r"(r) : "f"(f));
    return r;
}

__device__ __forceinline__ void mma_tf32(float acc[4], const uint32_t a[4],
                                         uint32_t b0, uint32_t b1) {
    asm volatile(
        "mma.sync.aligned.m16n8k8.row.col.f32.tf32.tf32.f32 "
        "{%0,%1,%2,%3},{%4,%5,%6,%7},{%8,%9},{%0,%1,%2,%3};"
        : "+f"(acc[0]), "+f"(acc[1]), "+f"(acc[2]), "+f"(acc[3])
        : "r"(a[0]), "r"(a[1]), "r"(a[2]), "r"(a[3]), "r"(b0), "r"(b1));
}

// ldmatrix x4 on 32-bit data: four 8-row x 16-byte windows.
__device__ __forceinline__ void ldsm4(uint32_t r[4], uint32_t addr) {
    asm volatile(
        "ldmatrix.sync.aligned.m8n8.x4.shared.b16 {%0,%1,%2,%3}, [%4];"
        : "=r"(r[0]), "=r"(r[1]), "=r"(r[2]), "=r"(r[3]) : "r"(addr));
}

__device__ __forceinline__ void cp16(uint32_t dst, const void* src) {
    asm volatile("cp.async.ca.shared.global [%0], [%1], 16;"
                 :: "r"(dst), "l"(src));
}
#define CP_COMMIT() asm volatile("cp.async.commit_group;" ::: "memory")
#define CP_WAIT1()  asm volatile("cp.async.wait_group 1;" ::: "memory")
#define CP_WAIT0()  asm volatile("cp.async.wait_group 0;" ::: "memory")

__device__ __forceinline__ bool better(float v, int k, float m, int km) {
    return v < m || (v == m && k < km);
}
// merge top-2 (b1,b2 sorted) into (a1,a2 sorted)
__device__ __forceinline__ void merge2(float& a1, int& ka1, float& a2, int& ka2,
                                       float b1, int kb1, float b2, int kb2) {
    if (better(b1, kb1, a1, ka1)) {
        float t1 = a1; int tk1 = ka1;
        a1 = b1; ka1 = kb1;
        if (better(t1, tk1, b2, kb2)) { a2 = t1; ka2 = tk1; }
        else                          { a2 = b2; ka2 = kb2; }
    } else if (better(b1, kb1, a2, ka2)) {
        a2 = b1; ka2 = kb1;
    }
}

// ---------------------------------------------------------------------------
// K0: per-codeword squared norm (exact fp32, sequential ref order)
__global__ void k_sc(const float* __restrict__ cb) {
    int t = blockIdx.x * 256 + threadIdx.x;
    const float* row = cb + (size_t)t * D_;
    float s = 0.f;
    for (int j = 0; j < D_; j++) {
        float q = __fmul_rn(row[j], row[j]);
        s = __fadd_rn(s, q);
    }
    g_sc[t] = s;
}

// no-op shim: keeps k_mma at profiled launch index 3
__global__ void k_nop() {}

// ---------------------------------------------------------------------------
// K1: tf32 mma.sync GEMM (R14 config: MT=128, 8 warps = 4m x 2k, 32x16 warp
// tiles, cp.async double-buffered TKC=32, ldmatrix, +0x1000 RNA fix on B).
// NEW: K split in 2 halves via blockIdx.z -> 784 CTAs of half work pack into
// 304 slots as ~3 balanced sub-waves (vs 392 full CTAs = 2 quantized waves).
// Per-half top-2 stored separately; merged in k_rescue.
__global__ void __launch_bounds__(256, 2)
k_mma(const float* __restrict__ z, const float* __restrict__ cb,
      float* __restrict__ out) {
    extern __shared__ float sm[];
    uint32_t* sAu = (uint32_t*)(sm + OFF_A);
    float*    ssz = sm + OFF_SSZ;
    float*    sm1 = sm + OFF_SM1;
    int*      sk1 = (int*)(sm + OFF_SK1);
    float*    sm2 = sm + OFF_SM2;
    int*      sk2 = (int*)(sm + OFF_SK2);

    const int tid  = threadIdx.x;
    const int lane = tid & 31;
    const int wid  = tid >> 5;
    const int p    = blockIdx.y;
    const int h    = blockIdx.z;            // k-half
    const int n0   = blockIdx.x * MT;
    const int g    = lane >> 2;      // 0..7
    const int tig  = lane & 3;       // 0..3
    const int mw   = (wid & 3) * 32;        // warp m offset (4 m-warps)
    const int kw   = (wid >> 2) * 16;       // warp k offset within 32-chunk

    const uint32_t bByte0 = (uint32_t)__cvta_generic_to_shared(sm + OFF_B0);
    const float* cbp = cb + (size_t)p * K_ * D_ + (size_t)h * KH * D_;

    // A tile load + tf32(rna) convert (each thread: one row, every other j)
    {
        int r = tid & 127, j0 = tid >> 7;
        int n = n0 + r, b = n / HW_, hw = n - b * HW_;
        const float* zr = z + (size_t)(b * C_ + p * D_) * HW_ + hw;
#pragma unroll 4
        for (int i = 0; i < 64; i++) {
            int j = j0 + 2 * i;
            sAu[r * 132 + j] = f2tf32(zr[(size_t)j * HW_]);
        }
    }

    // prefetch chunks 0 and 1 (16 KB each: 4 x 16B per thread)
#pragma unroll
    for (int c0 = 0; c0 < 2; c0++) {
        const float* src = cbp + (size_t)c0 * TKC * D_;
        uint32_t dstB = bByte0 + (uint32_t)(c0 * (32 * 132 * 4));
#pragma unroll
        for (int i = 0; i < 4; i++) {
            int e = tid + 256 * i;
            int kr = e >> 5, j4 = e & 31;
            cp16(dstB + (uint32_t)((kr * 132 + j4 * 4) * 4),
                 src + (size_t)kr * D_ + j4 * 4);
        }
        CP_COMMIT();
    }

    // exact sz, strict sequential order (matches reference reduction order)
    if (tid < 128) {
        int r = tid, n = n0 + r, b = n / HW_, hw = n - b * HW_;
        const float* zr = z + (size_t)(b * C_ + p * D_) * HW_ + hw;
        float s = 0.f;
        for (int j = 0; j < D_; j++) {
            float v = zr[(size_t)j * HW_];
            s = __fadd_rn(s, __fmul_rn(v, v));
        }
        ssz[r] = s;
        g_szv[(size_t)(n0 + r) * 4 + p] = s;   // both halves write same value
    }
    __syncthreads();

    // per-thread row sz cache (rows: mw + 16*im + 8*rr + g, t = 2*im+rr)
    float szr[4];
#pragma unroll
    for (int t = 0; t < 4; t++)
        szr[t] = ssz[mw + 16 * (t >> 1) + 8 * (t & 1) + g];

    // ldmatrix lane-address setup (constant across chunks; +32B per k8-step)
    const int l7    = lane & 7;
    const int rselA = (lane >> 3) & 1;
    const int dselA = lane >> 4;
    const uint32_t aBase = (uint32_t)__cvta_generic_to_shared(sAu);
    uint32_t aAddr[2];
#pragma unroll
    for (int im = 0; im < 2; im++) {
        int row = mw + 16 * im + 8 * rselA + l7;
        aAddr[im] = aBase + (uint32_t)((row * 132 + 4 * dselA) * 4);
    }
    uint32_t bAddr[2];
    {
        int row = kw + 8 * (lane >> 4) + l7;
        uint32_t o = (uint32_t)((row * 132 + 4 * ((lane >> 3) & 1)) * 4);
        bAddr[0] = bByte0 + o;
        bAddr[1] = bByte0 + (uint32_t)(32 * 132 * 4) + o;
    }

    float m1v[4], m2v[4];
    int   k1v[4], k2v[4];
#pragma unroll
    for (int t = 0; t < 4; t++) {
        m1v[t] = FLT_MAX; m2v[t] = FLT_MAX; k1v[t] = 0; k2v[t] = 0;
    }

    float* prob = out + PROB_OFF;
    const float* scg = g_sc + p * K_;

    for (int c = 0; c < NCHUNK; c++) {
        const int buf = c & 1;
        if (c < NCHUNK - 1) { CP_WAIT1(); } else { CP_WAIT0(); }
        __syncthreads();

        float acc[2][2][4];
#pragma unroll
        for (int im = 0; im < 2; im++)
#pragma unroll
            for (int j = 0; j < 2; j++)
#pragma unroll
                for (int q = 0; q < 4; q++) acc[im][j][q] = 0.f;

#pragma unroll
        for (int s = 0; s < 16; s++) {
            const uint32_t off = (uint32_t)(s * 32);   // 8 floats per k8-step
            uint32_t a0[4], a1[4], bb[4];
            ldsm4(a0, aAddr[0] + off);
            ldsm4(a1, aAddr[1] + off);
            ldsm4(bb, bAddr[buf] + off);
            // RNA-equivalent rounding of raw fp32 B at the tf32 boundary
            bb[0] += 0x1000u; bb[1] += 0x1000u;
            bb[2] += 0x1000u; bb[3] += 0x1000u;
            mma_tf32(acc[0][0], a0, bb[0], bb[1]);
            mma_tf32(acc[1][0], a1, bb[0], bb[1]);
            mma_tf32(acc[0][1], a0, bb[2], bb[3]);
            mma_tf32(acc[1][1], a1, bb[2], bb[3]);
        }
        __syncthreads();   // all reads of buf done -> safe to overwrite

        // prefetch chunk c+2 into this buffer
        if (c + 2 < NCHUNK) {
            const float* src = cbp + (size_t)(c + 2) * TKC * D_;
            uint32_t dstB = bByte0 + (uint32_t)(buf * (32 * 132 * 4));
#pragma unroll
            for (int i = 0; i < 4; i++) {
                int e = tid + 256 * i;
                int kr = e >> 5, j4 = e & 31;
                cp16(dstB + (uint32_t)((kr * 132 + j4 * 4) * 4),
                     src + (size_t)kr * D_ + j4 * 4);
            }
        }
        CP_COMMIT();   // commit every chunk (possibly empty) to keep count

        // epilogue: dist, scalar streaming stores, top-2 update
        const int kc = h * KH + c * TKC + kw;
#pragma unroll
        for (int im = 0; im < 2; im++) {
#pragma unroll
            for (int rr = 0; rr < 2; rr++) {
                const int t = 2 * im + rr;
                const float sz_ = szr[t];
                const int rowg = n0 + mw + 16 * im + 8 * rr + g;
                float* prow = prob + (size_t)rowg * 8192 + p * 2048;
#pragma unroll
                for (int j = 0; j < 2; j++) {
                    int k = kc + 8 * j + 2 * tig;
                    float sc0 = __ldg(scg + k);
                    float sc1 = __ldg(scg + k + 1);
                    float d0v = __fmaf_rn(-2.f, acc[im][j][2 * rr],
                                          __fadd_rn(sz_, sc0));
                    float d1v = __fmaf_rn(-2.f, acc[im][j][2 * rr + 1],
                                          __fadd_rn(sz_, sc1));
                    __stcs(prow + k,     d0v);
                    __stcs(prow + k + 1, d1v);
                    if (better(d0v, k, m1v[t], k1v[t])) {
                        m2v[t] = m1v[t]; k2v[t] = k1v[t];
                        m1v[t] = d0v;    k1v[t] = k;
                    } else if (better(d0v, k, m2v[t], k2v[t])) {
                        m2v[t] = d0v; k2v[t] = k;
                    }
                    if (better(d1v, k + 1, m1v[t], k1v[t])) {
                        m2v[t] = m1v[t]; k2v[t] = k1v[t];
                        m1v[t] = d1v;    k1v[t] = k + 1;
                    } else if (better(d1v, k + 1, m2v[t], k2v[t])) {
                        m2v[t] = d1v; k2v[t] = k + 1;
                    }
                }
            }
        }
    }

    // quad merge (lanes sharing the same rows: same g, tig 0..3)
#pragma unroll
    for (int t = 0; t < 4; t++) {
#pragma unroll
        for (int off = 1; off <= 2; off <<= 1) {
            float o1 = __shfl_xor_sync(0xffffffffu, m1v[t], off);
            int  ok1 = __shfl_xor_sync(0xffffffffu, k1v[t], off);
            float o2 = __shfl_xor_sync(0xffffffffu, m2v[t], off);
            int  ok2 = __shfl_xor_sync(0xffffffffu, k2v[t], off);
            merge2(m1v[t], k1v[t], m2v[t], k2v[t], o1, ok1, o2, ok2);
        }
    }
    __syncthreads();
    if (tig == 0) {
        int kg = wid >> 2;
#pragma unroll
        for (int t = 0; t < 4; t++) {
            int row = mw + 16 * (t >> 1) + 8 * (t & 1) + g;
            int idx = kg * 128 + row;
            sm1[idx] = m1v[t]; sk1[idx] = k1v[t];
            sm2[idx] = m2v[t]; sk2[idx] = k2v[t];
        }
    }
    __syncthreads();
    if (tid < 128) {
        float a1 = sm1[tid], a2 = sm2[tid];
        int  ka1 = sk1[tid], ka2 = sk2[tid];
        merge2(a1, ka1, a2, ka2, sm1[128 + tid], sk1[128 + tid],
               sm2[128 + tid], sk2[128 + tid]);
        size_t idx2 = ((size_t)(n0 + tid) * 4 + p) * 2 + h;
        g_m1h[idx2] = a1;
        g_k1h[idx2] = ka1;
        g_m2h[idx2] = a2;
        g_k2h[idx2] = ka2;
    }
}

// ---------------------------------------------------------------------------
// K1b: merge the two k-halves' top-2, then exact-fp32 argmin rescue for
// near-tie rows. One warp per rho (all lanes redo the cheap merge; loads
// are broadcast).
__global__ void __launch_bounds__(128)
k_rescue(const float* __restrict__ z, const float* __restrict__ cb) {
    int w    = threadIdx.x >> 5;
    int lane = threadIdx.x & 31;
    int rho  = blockIdx.x * 4 + w;

    size_t i0 = (size_t)rho * 2;
    float m1 = g_m1h[i0], m2 = g_m2h[i0];
    int   k1 = g_k1h[i0], k2 = g_k2h[i0];
    merge2(m1, k1, m2, k2, g_m1h[i0 + 1], g_k1h[i0 + 1],
           g_m2h[i0 + 1], g_k2h[i0 + 1]);

    if (lane == 0) g_minD[rho] = m1;

    if (!(m2 - m1 < EPS_RESCUE)) {
        if (lane == 0) g_idx[rho] = k1;
        return;
    }

    int n = rho >> 2, p = rho & 3;
    int b = n / HW_, hw = n - b * HW_;
    const float* zr  = z + (size_t)(b * C_ + p * D_) * HW_ + hw;
    const float* c1r = cb + (size_t)(p * K_ + k1) * D_;
    const float* c2r = cb + (size_t)(p * K_ + k2) * D_;

    float a1 = 0.f, a2 = 0.f;
#pragma unroll
    for (int t = 0; t < 4; t++) {
        int j = lane + 32 * t;
        float zv = zr[(size_t)j * HW_];
        a1 = __fmaf_rn(zv, c1r[j], a1);
        a2 = __fmaf_rn(zv, c2r[j], a2);
    }
    for (int o = 16; o; o >>= 1) {
        a1 += __shfl_xor_sync(0xffffffffu, a1, o);
        a2 += __shfl_xor_sync(0xffffffffu, a2, o);
    }
    if (lane == 0) {
        float sz = g_szv[rho];
        float d1 = __fmaf_rn(-2.f, a1, __fadd_rn(sz, g_sc[p * K_ + k1]));
        float d2 = __fmaf_rn(-2.f, a2, __fadd_rn(sz, g_sc[p * K_ + k2]));
        int pick = (d1 < d2 || (d1 == d2 && k1 < k2)) ? k1 : k2;
        g_idx[rho] = pick;
    }
}

// ---------------------------------------------------------------------------
// K2: in-place softmax normalize. One 64-thread group per row (4 rows/CTA).
__global__ void __launch_bounds__(256)
k_norm(float* __restrict__ out) {
    int g      = threadIdx.x >> 6;
    int lane64 = threadIdx.x & 63;
    int rho    = blockIdx.x * 4 + g;
    float* row = out + PROB_OFF + (size_t)rho * 2048;
    float m = g_minD[rho];

    float e[32];
    float s = 0.f;
#pragma unroll 4
    for (int ii = 0; ii < 32; ii++) {
        float dist = row[lane64 + 64 * ii];
        float ev = expf(2.f * (m - dist));
        e[ii] = ev;
        s += ev;
    }
    for (int o = 16; o; o >>= 1) s += __shfl_down_sync(0xffffffffu, s, o);
    __shared__ float wsum[8];
    if ((threadIdx.x & 31) == 0) wsum[threadIdx.x >> 5] = s;
    __syncthreads();
    float S = wsum[2 * g] + wsum[2 * g + 1];
    float inv = 1.0f / S;
#pragma unroll 4
    for (int ii = 0; ii < 32; ii++) row[lane64 + 64 * ii] = e[ii] * inv;
}

// ---------------------------------------------------------------------------
// K3: zq_out (straight-through, fl(zf + fl(zq - zf))) + per-CTA loss partials.
__global__ void __launch_bounds__(256)
k_zq(const float* __restrict__ z, const float* __restrict__ cb,
     float* __restrict__ out) {
    __shared__ float cz[TN][D_];
    __shared__ int   sidx[TN];
    __shared__ float lred[256];

    const int tile = blockIdx.x;
    const int p    = blockIdx.y;
    const int tid  = threadIdx.x;
    const int n0   = tile * TN;

    if (tid < TN) sidx[tid] = g_idx[(n0 + tid) * 4 + p];
    __syncthreads();

    for (int e = tid; e < TN * (D_ / 4); e += 256) {
        int r  = e >> 5;
        int j4 = e & 31;
        float4 v = *(const float4*)(cb + ((size_t)(p * K_ + sidx[r]) * D_) + j4 * 4);
        cz[r][j4 * 4 + 0] = v.x; cz[r][j4 * 4 + 1] = v.y;
        cz[r][j4 * 4 + 2] = v.z; cz[r][j4 * 4 + 3] = v.w;
    }
    __syncthreads();

    float ls = 0.f;
    for (int e = tid; e < TN * D_; e += 256) {
        int j = e >> 6;
        int r = e & 63;
        int n = n0 + r;
        int b = n / HW_;
        int hw = n - b * HW_;
        size_t ga = (size_t)(b * C_ + p * D_ + j) * HW_ + hw;
        float zf = z[ga];
        float d  = __fsub_rn(cz[r][j], zf);
        out[ga]  = __fadd_rn(zf, d);
        ls = __fadd_rn(ls, __fmul_rn(d, d));
    }
    lred[tid] = ls;
    __syncthreads();
    for (int o = 128; o; o >>= 1) {
        if (tid < o) lred[tid] += lred[tid + o];
        __syncthreads();
    }
    if (tid == 0) g_losspart[p * NTILE + tile] = lred[0];
}

// ---------------------------------------------------------------------------
// K4: final deterministic loss reduction. q = m + fl(0.25*m).
__global__ void k_loss(float* __restrict__ out) {
    __shared__ float s[256];
    int tid = threadIdx.x;
    float a = 0.f;
    for (int e = tid; e < NTILE * P_; e += 256) a += g_losspart[e];
    s[tid] = a;
    __syncthreads();
    for (int o = 128; o; o >>= 1) {
        if (tid < o) s[tid] += s[tid + o];
        __syncthreads();
    }
    if (tid == 0) {
        float m = s[0] / 6422528.0f;
        out[LOSS_OFF] = __fadd_rn(m, __fmul_rn(0.25f, m));
    }
}

// ---------------------------------------------------------------------------
extern "C" void kernel_launch(void* const* d_in, const int* in_sizes, int n_in,
                              void* d_out, int out_size) {
    const float* z  = (const float*)d_in[0];   // [16,512,28,28]
    const float* cb = (const float*)d_in[1];   // [4,2048,128]
    float* out = (float*)d_out;

    const int smem_mma = SMEM_FLOATS * (int)sizeof(float);
    cudaFuncSetAttribute(k_mma, cudaFuncAttributeMaxDynamicSharedMemorySize, smem_mma);

    k_sc<<<32, 256>>>(cb);
    k_nop<<<1, 32>>>();          // shims: keep k_mma at profiled launch idx 3
    k_nop<<<1, 32>>>();
    k_mma<<<dim3(MTILE, P_, 2), 256, smem_mma>>>(z, cb, out);
    k_rescue<<<NP_ / 4, 128>>>(z, cb);
    k_norm<<<N_, 256>>>(out);
    k_zq<<<dim3(NTILE, P_), 256>>>(z, cb, out);
    k_loss<<<1, 256>>>(out);
}